// round 7
// baseline (speedup 1.0000x reference)
#include <cuda_runtime.h>
#include <cuda_bf16.h>
#include <math.h>
#include <stdint.h>

#define Bsz 256
#define Slen 128
#define Fdim 128
#define Hdim 512
#define Cdim 64
#define Ldim 16
#define KTOT 640
#define NCH 10

#define ROWB 144                     // A smem row stride bytes
#define WROWB 1296                   // W smem row stride bytes (640*2 + 16)
#define WHALF (64 * WROWB)           // 82944 per half (hi or lo)
#define AHALF (64 * ROWB)            // 9216
#define ABUF  (2 * AHALF)            // 18432 (hi+lo)
#define AOFF  (2 * WHALF)            // 165888
#define BIASOFF (AOFF + 3 * ABUF)    // 221184
#define SMEM_TOTAL (BIASOFF + 256)   // 221440
#define CST 68

// -------- device globals (no runtime allocation allowed) --------
__device__ __align__(16) __nv_bfloat16 g_Wh[2048 * KTOT];
__device__ __align__(16) __nv_bfloat16 g_Wl[2048 * KTOT];
__device__ __align__(16) __nv_bfloat16 g_xh[Bsz * Slen * Fdim];
__device__ __align__(16) __nv_bfloat16 g_xl[Bsz * Slen * Fdim];
__device__ __align__(16) __nv_bfloat16 g_hh[2][Bsz * Hdim];
__device__ __align__(16) __nv_bfloat16 g_hl[2][Bsz * Hdim];
__device__ float g_c[Bsz * Hdim];
__device__ float g_ctx[Bsz * 3 * Hdim];
__device__ int g_count;
__device__ volatile int g_flag;

__device__ __forceinline__ uint32_t smem_u32(const void* p) {
    uint32_t a;
    asm("{ .reg .u64 t; cvta.to.shared.u64 t, %1; cvt.u32.u64 %0, t; }" : "=r"(a) : "l"(p));
    return a;
}
__device__ __forceinline__ void cp16(uint32_t sdst, const void* gsrc) {
    asm volatile("cp.async.cg.shared.global [%0], [%1], 16;" :: "r"(sdst), "l"(gsrc));
}
#define CP_COMMIT() asm volatile("cp.async.commit_group;" ::: "memory")
#define CP_WAIT(n)  asm volatile("cp.async.wait_group %0;" :: "n"(n) : "memory")

__device__ __forceinline__ void mma16816(float c[4], const uint32_t a[4], const uint32_t b[2]) {
    asm volatile(
        "mma.sync.aligned.m16n8k16.row.col.f32.bf16.bf16.f32 "
        "{%0,%1,%2,%3}, {%4,%5,%6,%7}, {%8,%9}, {%0,%1,%2,%3};"
        : "+f"(c[0]), "+f"(c[1]), "+f"(c[2]), "+f"(c[3])
        : "r"(a[0]), "r"(a[1]), "r"(a[2]), "r"(a[3]), "r"(b[0]), "r"(b[1]));
}

__device__ __forceinline__ float sigf(float x) {
    return __fdividef(1.0f, 1.0f + __expf(-x));
}
__device__ __forceinline__ float tanh_fast(float x) {
    float xc = fminf(fmaxf(x, -15.0f), 15.0f);
    float e = __expf(2.0f * xc);
    return __fdividef(e - 1.0f, e + 1.0f);
}

// ---------------------------------------------------------------------------
// ONE persistent kernel: prep + 128 LSTM steps + VAE head.
// grid (32,4) = 128 CTAs (all resident), 256 threads, ~216KB smem.
// ---------------------------------------------------------------------------
__global__ __launch_bounds__(256) void vae_persist(
    const float* __restrict__ x, const float* __restrict__ context,
    const float* __restrict__ eps,
    const float* __restrict__ W_ih, const float* __restrict__ b_ih,
    const float* __restrict__ W_hh, const float* __restrict__ b_hh,
    const float* __restrict__ cg_w1, const float* __restrict__ cg_b1,
    const float* __restrict__ cg_w2, const float* __restrict__ cg_b2,
    const float* __restrict__ mu_w, const float* __restrict__ mu_b,
    const float* __restrict__ lv_w, const float* __restrict__ lv_b,
    const float* __restrict__ dec_w1, const float* __restrict__ dec_b1,
    const float* __restrict__ dec_w2, const float* __restrict__ dec_b2,
    float* __restrict__ out)
{
    extern __shared__ char smem[];
    const uint32_t sb = smem_u32(smem);
    const int tid = threadIdx.x;
    const int wid = tid >> 5, lane = tid & 31;
    const int wm = wid & 3, wn = wid >> 2;
    const int gID = lane >> 2, tid4 = lane & 3;
    const int bx = blockIdx.x, by = blockIdx.y;
    const int rank = by * 32 + bx;
    const int n0 = bx * 64, hcol0 = bx * 16, b0 = by * 64;

    __shared__ int s_base;
    if (tid == 0) s_base = g_flag;
    __syncthreads();
    const int base = s_base;
    int nbar = 0;

    auto gbar = [&]() {
        nbar++;
        const int target = base + nbar;
        __syncthreads();
        if (tid == 0) {
            __threadfence();
            if (atomicAdd(&g_count, 1) == 127) {
                atomicExch(&g_count, 0);
                __threadfence();
                g_flag = target;
            } else {
                while (g_flag < target) { }
            }
            __threadfence();
        }
        __syncthreads();
    };

    // ================= Phase A: prep (uses low smem, W not loaded yet) ======
    // zero state: 1024 elems per CTA
#pragma unroll
    for (int i = 0; i < 4; i++) {
        int idx = rank * 1024 + i * 256 + tid;
        g_c[idx] = 0.0f;
        g_hh[0][idx] = __float2bfloat16(0.0f);
        g_hl[0][idx] = __float2bfloat16(0.0f);
    }
    // split W (permuted n' = hcol*4 + gate): 10240 elems per CTA
    for (int i = 0; i < 40; i++) {
        int idx = rank * 10240 + i * 256 + tid;
        int np = idx / KTOT, k = idx - np * KTOT;
        int n = (np & 3) * Hdim + (np >> 2);
        float v = (k < Hdim) ? W_hh[k * 2048 + n] : W_ih[(k - Hdim) * 2048 + n];
        __nv_bfloat16 hi = __float2bfloat16(v);
        g_Wh[idx] = hi;
        g_Wl[idx] = __float2bfloat16(v - __bfloat162float(hi));
    }
    // split x: 32768 elems per CTA
    for (int i = 0; i < 128; i++) {
        int idx = rank * 32768 + i * 256 + tid;
        float v = x[idx];
        __nv_bfloat16 hi = __float2bfloat16(v);
        g_xh[idx] = hi;
        g_xl[idx] = __float2bfloat16(v - __bfloat162float(hi));
    }
    // context gates for batch rows 2*rank, 2*rank+1
    {
        float* ctxrow = (float*)smem;              // 2 x 64
        float* tmp = (float*)(smem + 1024);        // 2 x 512
        if (tid < 128) {
            int row = tid >> 6, k = tid & 63;
            ctxrow[row * 64 + k] = context[(rank * 2 + row) * Cdim + k];
        }
        __syncthreads();
#pragma unroll
        for (int i = 0; i < 4; i++) {
            int idx = i * 256 + tid;
            int row = idx >> 9, n = idx & 511;
            float s = cg_b1[n];
            for (int k = 0; k < Cdim; k++) s += ctxrow[row * 64 + k] * cg_w1[k * Hdim + n];
            tmp[row * 512 + n] = fmaxf(s, 0.0f);
        }
        __syncthreads();
        for (int i = 0; i < 12; i++) {
            int idx = i * 256 + tid;
            int row = idx / 1536, n = idx - row * 1536;
            float s = cg_b2[n];
            const float* tr = tmp + row * 512;
            for (int k = 0; k < Hdim; k++) s += tr[k] * cg_w2[k * 1536 + n];
            g_ctx[(rank * 2 + row) * 1536 + n] = 1.0f / (1.0f + expf(-s));
        }
    }
    gbar();   // #1: all prep visible

    // ================= Phase B: load W tile (both halves) into smem ========
    if (tid < 64) {
        int np = n0 + tid;
        int n = (np & 3) * Hdim + (np >> 2);
        ((float*)(smem + BIASOFF))[tid] = b_ih[n] + b_hh[n];
    }
    for (int i = 0; i < 40; i++) {
        int j = i * 256 + tid;
        int half = j / 5120, rem = j - half * 5120;
        int row = rem / 80, q = rem - row * 80;
        uint32_t dst = sb + half * WHALF + row * WROWB + q * 16;
        const __nv_bfloat16* src = half ? g_Wl : g_Wh;
        cp16(dst, src + (size_t)(n0 + row) * KTOT + q * 8);
    }
    CP_COMMIT();

    // ================= LSTM steps ==========================================
    float acc[4][4];

    auto copyA = [&](int c, int t,
                     const __nv_bfloat16* hh, const __nv_bfloat16* hl) {
        const int kc = (c < 2) ? 8 + c : c - 2;       // x chunks first
        const uint32_t abase = sb + AOFF + (uint32_t)(c % 3) * ABUF;
#pragma unroll
        for (int half = 0; half < 2; half++) {
#pragma unroll
            for (int i = 0; i < 2; i++) {
                int idx = i * 256 + tid, r = idx >> 3, q = idx & 7;
                uint32_t dst = abase + half * AHALF + r * ROWB + q * 16;
                if (kc < 8) {
                    const __nv_bfloat16* src = half ? hl : hh;
                    cp16(dst, src + (size_t)(b0 + r) * Hdim + kc * 64 + q * 8);
                } else {
                    const __nv_bfloat16* src = half ? g_xl : g_xh;
                    cp16(dst, src + ((size_t)(b0 + r) * Slen + t) * Fdim + (kc - 8) * 64 + q * 8);
                }
            }
        }
    };

    auto compute = [&](int c) {
        const int kc = (c < 2) ? 8 + c : c - 2;
        const char* Ab = smem + AOFF + (c % 3) * ABUF;
        const int wcol = kc * 128;
#pragma unroll
        for (int ks = 0; ks < 4; ks++) {
            const int kb = ks * 32 + tid4 * 4;
            uint32_t ah[4], al[4];
            const char* ar = Ab + (wm * 16 + gID) * ROWB + kb;
            ah[0] = *(const uint32_t*)(ar);
            ah[2] = *(const uint32_t*)(ar + 16);
            ah[1] = *(const uint32_t*)(ar + 8 * ROWB);
            ah[3] = *(const uint32_t*)(ar + 8 * ROWB + 16);
            const char* arl = ar + AHALF;
            al[0] = *(const uint32_t*)(arl);
            al[2] = *(const uint32_t*)(arl + 16);
            al[1] = *(const uint32_t*)(arl + 8 * ROWB);
            al[3] = *(const uint32_t*)(arl + 8 * ROWB + 16);
#pragma unroll
            for (int j = 0; j < 4; j++) {
                const char* br = smem + (wn * 32 + j * 8 + gID) * WROWB + wcol + kb;
                uint32_t bh[2], bl[2];
                bh[0] = *(const uint32_t*)(br);
                bh[1] = *(const uint32_t*)(br + 16);
                bl[0] = *(const uint32_t*)(br + WHALF);
                bl[1] = *(const uint32_t*)(br + WHALF + 16);
                mma16816(acc[j], ah, bh);
                mma16816(acc[j], ah, bl);
                mma16816(acc[j], al, bh);
            }
        }
    };

    for (int t = 0; t < Slen; t++) {
        const __nv_bfloat16* hh = g_hh[t & 1];
        const __nv_bfloat16* hl = g_hl[t & 1];
        __nv_bfloat16* ohh = g_hh[(t + 1) & 1];
        __nv_bfloat16* ohl = g_hl[(t + 1) & 1];

#pragma unroll
        for (int j = 0; j < 4; j++)
#pragma unroll
            for (int r = 0; r < 4; r++) acc[j][r] = 0.0f;

        // prefetch x chunks (no h dependency) before the step barrier
        copyA(0, t, hh, hl); CP_COMMIT();
        copyA(1, t, hh, hl); CP_COMMIT();
        gbar();               // previous step's h now globally visible

        for (int c = 0; c < NCH; c++) {
            if (c + 2 < NCH) { copyA(c + 2, t, hh, hl); CP_COMMIT(); }
            if (c + 2 < NCH)      { CP_WAIT(2); }
            else if (c + 1 < NCH) { CP_WAIT(1); }
            else                  { CP_WAIT(0); }
            __syncthreads();
            compute(c);
            __syncthreads();
        }

        // ---- epilogue: acc -> Csm -> fused LSTM update ----
        float* Csm = (float*)(smem + AOFF);
#pragma unroll
        for (int j = 0; j < 4; j++) {
            int n = wn * 32 + j * 8 + tid4 * 2;
            int m0r = wm * 16 + gID;
            *(float2*)&Csm[m0r * CST + n]       = make_float2(acc[j][0], acc[j][1]);
            *(float2*)&Csm[(m0r + 8) * CST + n] = make_float2(acc[j][2], acc[j][3]);
        }
        __syncthreads();
        const float* bias = (const float*)(smem + BIASOFF);
#pragma unroll
        for (int it = 0; it < 4; it++) {
            int idx = it * 256 + tid;
            int m = idx >> 4, hcl = idx & 15;
            float4 gv = *(float4*)&Csm[m * CST + hcl * 4];
            float4 bb = *(const float4*)&bias[hcl * 4];
            int b = b0 + m, hc = hcol0 + hcl;
            const float* cxp = g_ctx + (size_t)b * 1536;
            float iv = sigf(gv.x + bb.x) * cxp[hc];
            float fv = sigf(gv.y + bb.y) * cxp[Hdim + hc];
            float gg = tanh_fast(gv.z + bb.z);
            float ov = sigf(gv.w + bb.w) * cxp[2 * Hdim + hc];
            float cn = fv * g_c[(size_t)b * Hdim + hc] + iv * gg;
            g_c[(size_t)b * Hdim + hc] = cn;
            float hv = ov * tanh_fast(cn);
            __nv_bfloat16 hhi = __float2bfloat16(hv);
            ohh[(size_t)b * Hdim + hc] = hhi;
            ohl[(size_t)b * Hdim + hc] = __float2bfloat16(hv - __bfloat162float(hhi));
        }
        __threadfence();
        __syncthreads();   // Csm reads done before next step's prefetch
    }

    gbar();   // final h visible everywhere

    // ================= VAE head: rows 2*rank, 2*rank+1 =====================
    {
        float* hrow = (float*)smem;                 // 2 x 512
        float* zv   = (float*)(smem + 4096);        // 2 x 16
        float* d1   = (float*)(smem + 4352);        // 2 x 512
#pragma unroll
        for (int i = 0; i < 4; i++) {
            int idx = i * 256 + tid;
            int row = idx >> 9, k = idx & 511;
            int b = rank * 2 + row;
            hrow[idx] = __bfloat162float(g_hh[0][(size_t)b * Hdim + k]) +
                        __bfloat162float(g_hl[0][(size_t)b * Hdim + k]);
        }
        __syncthreads();
        if (tid < 32) {
            int row = tid >> 4, j = tid & 15;
            int b = rank * 2 + row;
            const float* hr = hrow + row * 512;
            float m = mu_b[j];
            for (int k = 0; k < Hdim; k++) m += hr[k] * mu_w[k * Ldim + j];
            float lv = lv_b[j];
            for (int k = 0; k < Hdim; k++) lv += hr[k] * lv_w[k * Ldim + j];
            out[Bsz * Fdim + b * Ldim + j] = m;
            out[Bsz * Fdim + Bsz * Ldim + b * Ldim + j] = lv;
            zv[tid] = m + eps[b * Ldim + j] * expf(0.5f * lv);
        }
        __syncthreads();
#pragma unroll
        for (int i = 0; i < 4; i++) {
            int idx = i * 256 + tid;
            int row = idx >> 9, n = idx & 511;
            float s = dec_b1[n];
            const float* z = zv + row * 16;
#pragma unroll
            for (int k = 0; k < Ldim; k++) s += z[k] * dec_w1[k * Hdim + n];
            d1[idx] = fmaxf(s, 0.0f);
        }
        __syncthreads();
        {
            int row = tid >> 7, n = tid & 127;
            int b = rank * 2 + row;
            float s = dec_b2[n];
            const float* dr = d1 + row * 512;
            for (int k = 0; k < Hdim; k++) s += dr[k] * dec_w2[k * Fdim + n];
            out[(size_t)b * Fdim + n] = s;
        }
    }
}

// ---------------------------------------------------------------------------
extern "C" void kernel_launch(void* const* d_in, const int* in_sizes, int n_in,
                              void* d_out, int out_size)
{
    const float* x       = (const float*)d_in[0];
    const float* context = (const float*)d_in[1];
    const float* eps     = (const float*)d_in[2];
    const float* W_ih    = (const float*)d_in[3];
    const float* b_ih    = (const float*)d_in[4];
    const float* W_hh    = (const float*)d_in[5];
    const float* b_hh    = (const float*)d_in[6];
    const float* cg_w1   = (const float*)d_in[7];
    const float* cg_b1   = (const float*)d_in[8];
    const float* cg_w2   = (const float*)d_in[9];
    const float* cg_b2   = (const float*)d_in[10];
    const float* mu_w    = (const float*)d_in[11];
    const float* mu_b    = (const float*)d_in[12];
    const float* lv_w    = (const float*)d_in[13];
    const float* lv_b    = (const float*)d_in[14];
    const float* dec_w1  = (const float*)d_in[15];
    const float* dec_b1  = (const float*)d_in[16];
    const float* dec_w2  = (const float*)d_in[17];
    const float* dec_b2  = (const float*)d_in[18];
    float* out = (float*)d_out;

    cudaFuncSetAttribute(vae_persist, cudaFuncAttributeMaxDynamicSharedMemorySize,
                         SMEM_TOTAL);

    vae_persist<<<dim3(32, 4), 256, SMEM_TOTAL>>>(
        x, context, eps, W_ih, b_ih, W_hh, b_hh,
        cg_w1, cg_b1, cg_w2, cg_b2, mu_w, mu_b, lv_w, lv_b,
        dec_w1, dec_b1, dec_w2, dec_b2, out);
}